// round 2
// baseline (speedup 1.0000x reference)
#include <cuda_runtime.h>
#include <math.h>

#define NN    10000
#define EE    320000
#define FIN   7
#define DD    256
#define HH    8
#define CC    32
#define LL    2
#define GG    16
#define SLOPE 0.2f

// ---------------- scratch (static __device__, no allocation) ----------------
__device__ float g_h  [NN * DD];
__device__ float g_xl [NN * DD];
__device__ float g_xr [NN * DD];
__device__ int   g_deg   [NN];
__device__ int   g_rowptr[NN + 1];
__device__ int   g_cursor[NN];
__device__ int   g_csrc  [EE];
__device__ float g_pool  [GG * DD];
__device__ float g_cnt   [GG];

// ---------------- init ----------------
__global__ void zero_kernel() {
    int i = blockIdx.x * blockDim.x + threadIdx.x;
    int stride = gridDim.x * blockDim.x;
    for (int k = i; k < NN; k += stride)      g_deg[k] = 0;
    for (int k = i; k < GG * DD; k += stride) g_pool[k] = 0.f;
    if (i < GG) g_cnt[i] = 0.f;
}

// ---------------- h = x @ Wp + bp ----------------
__global__ void proj_kernel(const float* __restrict__ x,
                            const float* __restrict__ Wp,
                            const float* __restrict__ bp) {
    int n = blockIdx.x;
    int d = threadIdx.x;
    float acc = bp[d];
#pragma unroll
    for (int f = 0; f < FIN; ++f)
        acc += x[n * FIN + f] * Wp[f * DD + d];
    g_h[n * DD + d] = acc;
}

// ---------------- CSR build (edge_index is int32: JAX x64 is disabled) ------
__global__ void hist_kernel(const int* __restrict__ ei) {
    int e = blockIdx.x * blockDim.x + threadIdx.x;
    if (e < EE) atomicAdd(&g_deg[ei[EE + e]], 1);
}

__global__ void cnt_kernel(const int* __restrict__ batch) {
    int n = blockIdx.x * blockDim.x + threadIdx.x;
    if (n < NN) atomicAdd(&g_cnt[batch[n]], 1.0f);
}

__global__ void scan_kernel() {
    __shared__ int s[1024];
    const int tid = threadIdx.x;
    const int CH  = (NN + 1023) / 1024;   // 10
    const int base = tid * CH;
    int sum = 0;
    for (int k = 0; k < CH; ++k) {
        int idx = base + k;
        if (idx < NN) sum += g_deg[idx];
    }
    s[tid] = sum;
    __syncthreads();
    for (int off = 1; off < 1024; off <<= 1) {
        int v = (tid >= off) ? s[tid - off] : 0;
        __syncthreads();
        s[tid] += v;
        __syncthreads();
    }
    int run = s[tid] - sum;   // exclusive prefix of this chunk
    for (int k = 0; k < CH; ++k) {
        int idx = base + k;
        if (idx < NN) {
            g_rowptr[idx] = run;
            g_cursor[idx] = run;
            run += g_deg[idx];
        }
    }
    if (tid == 1023) g_rowptr[NN] = s[1023];
}

__global__ void scatter_kernel(const int* __restrict__ ei) {
    int e = blockIdx.x * blockDim.x + threadIdx.x;
    if (e < EE) {
        int d   = ei[EE + e];
        int pos = atomicAdd(&g_cursor[d], 1);
        g_csrc[pos] = ei[e];
    }
}

// ---------------- GEMM: C(= g_xl or g_xr) = g_h @ B,  [NN,DD] x [DD,DD] ----------------
#define BM 64
#define BN 64
#define BK 16
__global__ __launch_bounds__(256) void gemm_kernel(const float* __restrict__ B, int outsel) {
    __shared__ float As[BK][BM];
    __shared__ float Bs[BK][BN];
    float* C = outsel ? g_xr : g_xl;

    const int tid = threadIdx.x;
    const int tx  = tid & 15;
    const int ty  = tid >> 4;
    const int rowBase = blockIdx.y * BM;
    const int colBase = blockIdx.x * BN;

    float acc[4][4];
#pragma unroll
    for (int i = 0; i < 4; ++i)
#pragma unroll
        for (int j = 0; j < 4; ++j) acc[i][j] = 0.f;

    const int ar  = tid >> 2;   // 0..63  A tile row
    const int akq = tid & 3;    // 0..3   A k-quad
    const int bk  = tid >> 4;   // 0..15  B tile k
    const int bnq = tid & 15;   // 0..15  B n-quad

    for (int kt = 0; kt < DD; kt += BK) {
        float4 av;
        int gr = rowBase + ar;
        if (gr < NN) av = *(const float4*)(g_h + (size_t)gr * DD + kt + akq * 4);
        else         av = make_float4(0.f, 0.f, 0.f, 0.f);
        As[akq * 4 + 0][ar] = av.x;
        As[akq * 4 + 1][ar] = av.y;
        As[akq * 4 + 2][ar] = av.z;
        As[akq * 4 + 3][ar] = av.w;

        *(float4*)&Bs[bk][bnq * 4] =
            *(const float4*)(B + (size_t)(kt + bk) * DD + colBase + bnq * 4);
        __syncthreads();

#pragma unroll
        for (int kk = 0; kk < BK; ++kk) {
            float4 a = *(const float4*)&As[kk][ty * 4];
            float4 b = *(const float4*)&Bs[kk][tx * 4];
            acc[0][0] += a.x * b.x; acc[0][1] += a.x * b.y; acc[0][2] += a.x * b.z; acc[0][3] += a.x * b.w;
            acc[1][0] += a.y * b.x; acc[1][1] += a.y * b.y; acc[1][2] += a.y * b.z; acc[1][3] += a.y * b.w;
            acc[2][0] += a.z * b.x; acc[2][1] += a.z * b.y; acc[2][2] += a.z * b.z; acc[2][3] += a.z * b.w;
            acc[3][0] += a.w * b.x; acc[3][1] += a.w * b.y; acc[3][2] += a.w * b.z; acc[3][3] += a.w * b.w;
        }
        __syncthreads();
    }

#pragma unroll
    for (int i = 0; i < 4; ++i) {
        int row = rowBase + ty * 4 + i;
        if (row < NN) {
            float4 o = make_float4(acc[i][0], acc[i][1], acc[i][2], acc[i][3]);
            *(float4*)(C + (size_t)row * DD + colBase + tx * 4) = o;
        }
    }
}

// ---------------- GATv2 edge + online segment softmax + aggregate ----------------
// One warp per (node, head); lane = channel. Single pass, no float atomics.
__global__ __launch_bounds__(256) void gat_kernel(const float* __restrict__ att_l,
                                                  const float* __restrict__ bconv_l) {
    const int n = blockIdx.x;
    const int h = threadIdx.x >> 5;
    const int c = threadIdx.x & 31;
    const int d = h * CC + c;

    const int r0 = g_rowptr[n];
    const int r1 = g_rowptr[n + 1];

    const float xrv = g_xr[(size_t)n * DD + d];
    const float av  = att_l[d];

    float m = -INFINITY, ssum = 0.f, acc = 0.f;

    for (int k = r0; k < r1; ++k) {
        int s = g_csrc[k];
        float xlv = g_xl[(size_t)s * DD + d];
        float v = xlv + xrv;
        v = v > 0.f ? v : SLOPE * v;
        float p = v * av;
#pragma unroll
        for (int off = 16; off; off >>= 1)
            p += __shfl_xor_sync(0xffffffffu, p, off);
        // p = attention logit e for this (edge, head), identical on all lanes
        float nm = fmaxf(m, p);
        float sc = __expf(m - nm);     // 0 on first iter (m = -inf)
        float w  = __expf(p - nm);
        acc  = acc  * sc + w * xlv;
        ssum = ssum * sc + w;
        m = nm;
    }

    float out = (r1 > r0) ? (acc / ssum) : 0.f;
    g_h[(size_t)n * DD + d] += out + bconv_l[d];
}

// ---------------- global mean pool (run-compressed atomics) ----------------
__global__ void pool_kernel(const int* __restrict__ batch) {
    const int d = threadIdx.x;
    const int per = (NN + gridDim.x - 1) / gridDim.x;
    int n0 = blockIdx.x * per;
    int n1 = n0 + per; if (n1 > NN) n1 = NN;
    if (n0 >= n1) return;
    int cur = batch[n0];
    float accv = 0.f;
    for (int n = n0; n < n1; ++n) {
        int b = batch[n];
        if (b != cur) {
            atomicAdd(&g_pool[cur * DD + d], accv);
            accv = 0.f;
            cur = b;
        }
        accv += g_h[(size_t)n * DD + d];
    }
    atomicAdd(&g_pool[cur * DD + d], accv);
}

// ---------------- prediction head ----------------
__global__ void pred_kernel(const float* __restrict__ Wpred,
                            const float* __restrict__ bpred,
                            float* __restrict__ out) {
    const int g    = threadIdx.x >> 5;
    const int lane = threadIdx.x & 31;
    float s = 0.f;
    for (int d = lane; d < DD; d += 32)
        s += g_pool[g * DD + d] * Wpred[d];
#pragma unroll
    for (int off = 16; off; off >>= 1)
        s += __shfl_xor_sync(0xffffffffu, s, off);
    if (lane == 0)
        out[g] = s / fmaxf(g_cnt[g], 1.0f) + bpred[0];
}

// ---------------- launch ----------------
extern "C" void kernel_launch(void* const* d_in, const int* in_sizes, int n_in,
                              void* d_out, int out_size) {
    const float* x     = (const float*)d_in[0];
    const int*   ei    = (const int*)  d_in[1];
    const int*   batch = (const int*)  d_in[2];
    const float* Wp    = (const float*)d_in[3];
    const float* bp    = (const float*)d_in[4];
    const float* Wl    = (const float*)d_in[5];
    const float* Wr    = (const float*)d_in[6];
    const float* att   = (const float*)d_in[7];
    const float* bconv = (const float*)d_in[8];
    const float* Wpred = (const float*)d_in[9];
    const float* bpred = (const float*)d_in[10];
    float* out = (float*)d_out;

    zero_kernel<<<64, 256>>>();
    proj_kernel<<<NN, DD>>>(x, Wp, bp);
    hist_kernel<<<(EE + 255) / 256, 256>>>(ei);
    cnt_kernel<<<(NN + 255) / 256, 256>>>(batch);
    scan_kernel<<<1, 1024>>>();
    scatter_kernel<<<(EE + 255) / 256, 256>>>(ei);

    dim3 ggrid(DD / BN, (NN + BM - 1) / BM);
    for (int l = 0; l < LL; ++l) {
        gemm_kernel<<<ggrid, 256>>>(Wl + (size_t)l * DD * DD, 0);
        gemm_kernel<<<ggrid, 256>>>(Wr + (size_t)l * DD * DD, 1);
        gat_kernel<<<NN, 256>>>(att + l * HH * CC, bconv + l * DD);
    }

    pool_kernel<<<64, DD>>>(batch);
    pred_kernel<<<1, GG * 32>>>(Wpred, bpred, out);
}

// round 3
// speedup vs baseline: 1.5002x; 1.5002x over previous
#include <cuda_runtime.h>
#include <math.h>

#define NN    10000
#define EE    320000
#define FIN   7
#define DD    256
#define HH    8
#define CC    32
#define LL    2
#define GG    16
#define SLOPE 0.2f

// ---------------- scratch (static __device__, no allocation) ----------------
__device__ float g_h  [NN * DD];
__device__ float g_xl [NN * DD];
__device__ float g_xr [NN * DD];
__device__ int   g_deg   [NN];
__device__ int   g_rowptr[NN + 1];
__device__ int   g_cursor[NN];
__device__ int   g_csrc  [EE];
__device__ float g_pool  [GG * DD];
__device__ float g_cnt   [GG];

// ---------------- init ----------------
__global__ void zero_kernel() {
    int i = blockIdx.x * blockDim.x + threadIdx.x;
    int stride = gridDim.x * blockDim.x;
    for (int k = i; k < NN; k += stride)      g_deg[k] = 0;
    for (int k = i; k < GG * DD; k += stride) g_pool[k] = 0.f;
    if (i < GG) g_cnt[i] = 0.f;
}

// ---------------- h = x @ Wp + bp ----------------
__global__ void proj_kernel(const float* __restrict__ x,
                            const float* __restrict__ Wp,
                            const float* __restrict__ bp) {
    int n = blockIdx.x;
    int d = threadIdx.x;
    float acc = bp[d];
#pragma unroll
    for (int f = 0; f < FIN; ++f)
        acc += x[n * FIN + f] * Wp[f * DD + d];
    g_h[n * DD + d] = acc;
}

// ---------------- CSR build (edge_index is int32) ----------------
__global__ void hist_kernel(const int* __restrict__ ei) {
    int e = blockIdx.x * blockDim.x + threadIdx.x;
    if (e < EE) atomicAdd(&g_deg[ei[EE + e]], 1);
}

__global__ void scan_kernel() {
    __shared__ int s[1024];
    const int tid = threadIdx.x;
    const int CH  = (NN + 1023) / 1024;   // 10
    const int base = tid * CH;
    int sum = 0;
    for (int k = 0; k < CH; ++k) {
        int idx = base + k;
        if (idx < NN) sum += g_deg[idx];
    }
    s[tid] = sum;
    __syncthreads();
    for (int off = 1; off < 1024; off <<= 1) {
        int v = (tid >= off) ? s[tid - off] : 0;
        __syncthreads();
        s[tid] += v;
        __syncthreads();
    }
    int run = s[tid] - sum;   // exclusive prefix of this chunk
    for (int k = 0; k < CH; ++k) {
        int idx = base + k;
        if (idx < NN) {
            g_rowptr[idx] = run;
            g_cursor[idx] = run;
            run += g_deg[idx];
        }
    }
    if (tid == 1023) g_rowptr[NN] = s[1023];
}

__global__ void scatter_kernel(const int* __restrict__ ei) {
    int e = blockIdx.x * blockDim.x + threadIdx.x;
    if (e < EE) {
        int d   = ei[EE + e];
        int pos = atomicAdd(&g_cursor[d], 1);
        g_csrc[pos] = ei[e];
    }
}

// ---------------- fused GEMM: g_xl = g_h @ Bl, g_xr = g_h @ Br --------------
// 128x64 tile, 256 threads, 8x4 per thread. grid.x: 0..3 -> Bl, 4..7 -> Br.
#define BM 128
#define BN 64
#define BK 16
__global__ __launch_bounds__(256) void gemm_kernel(const float* __restrict__ Bl,
                                                   const float* __restrict__ Br) {
    __shared__ float As[BK][BM];
    __shared__ float Bs[BK][BN];

    const int tid = threadIdx.x;
    const int cb  = blockIdx.x;              // 0..7
    const float* B = (cb < 4) ? Bl : Br;
    float*       C = (cb < 4) ? g_xl : g_xr;
    const int colBase = (cb & 3) * BN;
    const int rowBase = blockIdx.y * BM;

    const int tx = tid & 15;                 // col quad  (0..15) -> 4 cols
    const int ty = tid >> 4;                 // row octet (0..15) -> 8 rows

    // A load mapping: thread -> (row = tid/2, khalf = (tid&1)*8)
    const int lrow = tid >> 1;
    const int lkh  = (tid & 1) * 8;
    // B load mapping: thread -> (k = tid/16, col quad = (tid&15)*4)
    const int bk  = tid >> 4;
    const int bc4 = (tid & 15) * 4;

    float acc[8][4];
#pragma unroll
    for (int i = 0; i < 8; ++i)
#pragma unroll
        for (int j = 0; j < 4; ++j) acc[i][j] = 0.f;

    for (int kt = 0; kt < DD; kt += BK) {
        int gr = rowBase + lrow;
        float4 a0, a1;
        if (gr < NN) {
            a0 = *(const float4*)(g_h + (size_t)gr * DD + kt + lkh);
            a1 = *(const float4*)(g_h + (size_t)gr * DD + kt + lkh + 4);
        } else {
            a0 = make_float4(0.f,0.f,0.f,0.f);
            a1 = a0;
        }
        As[lkh + 0][lrow] = a0.x; As[lkh + 1][lrow] = a0.y;
        As[lkh + 2][lrow] = a0.z; As[lkh + 3][lrow] = a0.w;
        As[lkh + 4][lrow] = a1.x; As[lkh + 5][lrow] = a1.y;
        As[lkh + 6][lrow] = a1.z; As[lkh + 7][lrow] = a1.w;

        *(float4*)&Bs[bk][bc4] =
            *(const float4*)(B + (size_t)(kt + bk) * DD + colBase + bc4);
        __syncthreads();

#pragma unroll
        for (int kk = 0; kk < BK; ++kk) {
            float4 av0 = *(const float4*)&As[kk][ty * 8];
            float4 av1 = *(const float4*)&As[kk][ty * 8 + 4];
            float4 bv  = *(const float4*)&Bs[kk][tx * 4];
            float a[8] = {av0.x, av0.y, av0.z, av0.w, av1.x, av1.y, av1.z, av1.w};
#pragma unroll
            for (int i = 0; i < 8; ++i) {
                acc[i][0] += a[i] * bv.x;
                acc[i][1] += a[i] * bv.y;
                acc[i][2] += a[i] * bv.z;
                acc[i][3] += a[i] * bv.w;
            }
        }
        __syncthreads();
    }

#pragma unroll
    for (int i = 0; i < 8; ++i) {
        int row = rowBase + ty * 8 + i;
        if (row < NN) {
            float4 o = make_float4(acc[i][0], acc[i][1], acc[i][2], acc[i][3]);
            *(float4*)(C + (size_t)row * DD + colBase + tx * 4) = o;
        }
    }
}

// ---------------- GATv2 edge softmax + aggregate (4 heads per warp) ---------
// Warp handles (node, half): 128 channels. Lane = 4 channels (float4).
// 8-lane groups = one head; logit reduced with 3 shfls; plain exp (logits tiny,
// identical to max-shifted softmax up to fp rounding).
__global__ __launch_bounds__(256) void gat_kernel(const float* __restrict__ att_l,
                                                  const float* __restrict__ bconv_l) {
    const int w    = threadIdx.x >> 5;
    const int lane = threadIdx.x & 31;
    const int n    = blockIdx.x * 4 + (w >> 1);
    const int half = w & 1;
    const int d    = half * 128 + lane * 4;

    const int r0 = g_rowptr[n];
    const int r1 = g_rowptr[n + 1];

    const float4 xr4  = *(const float4*)&g_xr[(size_t)n * DD + d];
    const float4 att4 = *(const float4*)&att_l[d];

    float4 acc = make_float4(0.f, 0.f, 0.f, 0.f);
    float ssum = 0.f;

    for (int k = r0; k < r1; ++k) {
        int s = g_csrc[k];
        float4 xl4 = *(const float4*)&g_xl[(size_t)s * DD + d];
        float vx = xl4.x + xr4.x, vy = xl4.y + xr4.y;
        float vz = xl4.z + xr4.z, vw = xl4.w + xr4.w;
        float p = fmaxf(vx, SLOPE * vx) * att4.x
                + fmaxf(vy, SLOPE * vy) * att4.y
                + fmaxf(vz, SLOPE * vz) * att4.z
                + fmaxf(vw, SLOPE * vw) * att4.w;
        p += __shfl_xor_sync(0xffffffffu, p, 1);
        p += __shfl_xor_sync(0xffffffffu, p, 2);
        p += __shfl_xor_sync(0xffffffffu, p, 4);
        float wgt = __expf(p);
        acc.x += wgt * xl4.x; acc.y += wgt * xl4.y;
        acc.z += wgt * xl4.z; acc.w += wgt * xl4.w;
        ssum  += wgt;
    }

    const float inv = (r1 > r0) ? (1.f / ssum) : 0.f;
    const float4 bc4 = *(const float4*)&bconv_l[d];
    float4 hv = *(float4*)&g_h[(size_t)n * DD + d];
    hv.x += acc.x * inv + bc4.x;
    hv.y += acc.y * inv + bc4.y;
    hv.z += acc.z * inv + bc4.z;
    hv.w += acc.w * inv + bc4.w;
    *(float4*)&g_h[(size_t)n * DD + d] = hv;
}

// ---------------- global mean pool + per-graph count (run-compressed) -------
__global__ void pool_kernel(const int* __restrict__ batch) {
    const int d = threadIdx.x;
    const int per = (NN + gridDim.x - 1) / gridDim.x;
    int n0 = blockIdx.x * per;
    int n1 = n0 + per; if (n1 > NN) n1 = NN;
    if (n0 >= n1) return;
    int cur = batch[n0];
    float accv = 0.f;
    int   cc   = 0;
    for (int n = n0; n < n1; ++n) {
        int b = batch[n];
        if (b != cur) {
            atomicAdd(&g_pool[cur * DD + d], accv);
            if (d == 0) atomicAdd(&g_cnt[cur], (float)cc);
            accv = 0.f; cc = 0;
            cur = b;
        }
        accv += g_h[(size_t)n * DD + d];
        cc   += 1;
    }
    atomicAdd(&g_pool[cur * DD + d], accv);
    if (d == 0) atomicAdd(&g_cnt[cur], (float)cc);
}

// ---------------- prediction head ----------------
__global__ void pred_kernel(const float* __restrict__ Wpred,
                            const float* __restrict__ bpred,
                            float* __restrict__ out) {
    const int g    = threadIdx.x >> 5;
    const int lane = threadIdx.x & 31;
    float s = 0.f;
    for (int d = lane; d < DD; d += 32)
        s += g_pool[g * DD + d] * Wpred[d];
#pragma unroll
    for (int off = 16; off; off >>= 1)
        s += __shfl_xor_sync(0xffffffffu, s, off);
    if (lane == 0)
        out[g] = s / fmaxf(g_cnt[g], 1.0f) + bpred[0];
}

// ---------------- launch ----------------
extern "C" void kernel_launch(void* const* d_in, const int* in_sizes, int n_in,
                              void* d_out, int out_size) {
    const float* x     = (const float*)d_in[0];
    const int*   ei    = (const int*)  d_in[1];
    const int*   batch = (const int*)  d_in[2];
    const float* Wp    = (const float*)d_in[3];
    const float* bp    = (const float*)d_in[4];
    const float* Wl    = (const float*)d_in[5];
    const float* Wr    = (const float*)d_in[6];
    const float* att   = (const float*)d_in[7];
    const float* bconv = (const float*)d_in[8];
    const float* Wpred = (const float*)d_in[9];
    const float* bpred = (const float*)d_in[10];
    float* out = (float*)d_out;

    zero_kernel<<<64, 256>>>();
    proj_kernel<<<NN, DD>>>(x, Wp, bp);
    hist_kernel<<<(EE + 255) / 256, 256>>>(ei);
    scan_kernel<<<1, 1024>>>();
    scatter_kernel<<<(EE + 255) / 256, 256>>>(ei);

    dim3 ggrid(8, (NN + BM - 1) / BM);   // 8 col-blocks: 4 xl + 4 xr
    for (int l = 0; l < LL; ++l) {
        gemm_kernel<<<ggrid, 256>>>(Wl + (size_t)l * DD * DD,
                                    Wr + (size_t)l * DD * DD);
        gat_kernel<<<NN / 4, 256>>>(att + l * HH * CC, bconv + l * DD);
    }

    pool_kernel<<<64, DD>>>(batch);
    pred_kernel<<<1, GG * 32>>>(Wpred, bpred, out);
}

// round 6
// speedup vs baseline: 1.7304x; 1.1534x over previous
#include <cuda_runtime.h>
#include <cuda_bf16.h>
#include <math.h>
#include <stdint.h>

#define NN    10000
#define EE    320000
#define FIN   7
#define DD    256
#define HH    8
#define CC    32
#define LL    2
#define GG    16
#define SLOPE 0.2f

// ---------------- scratch (static __device__, no allocation) ----------------
__device__ float g_h  [NN * DD];
__device__ float g_xl [NN * DD];
__device__ float g_xr [NN * DD];
__device__ __align__(16) __nv_bfloat16 g_hh[NN * DD];
__device__ __align__(16) __nv_bfloat16 g_hl[NN * DD];
__device__ __align__(16) __nv_bfloat16 g_wh[2 * DD * DD];   // [sel][j][k] = W[k][j]
__device__ __align__(16) __nv_bfloat16 g_wl[2 * DD * DD];
__device__ int   g_deg   [NN];
__device__ int   g_rowptr[NN + 1];
__device__ int   g_cursor[NN];
__device__ int   g_csrc  [EE];
__device__ float g_pool  [GG * DD];
__device__ float g_cnt   [GG];

// ---------------- init ----------------
__global__ void zero_kernel() {
    int i = blockIdx.x * blockDim.x + threadIdx.x;
    int stride = gridDim.x * blockDim.x;
    for (int k = i; k < NN; k += stride)      g_deg[k] = 0;
    for (int k = i; k < GG * DD; k += stride) g_pool[k] = 0.f;
    if (i < GG) g_cnt[i] = 0.f;
}

// ---------------- h = x @ Wp + bp (+ bf16 hi/lo split) ----------------
__global__ void proj_kernel(const float* __restrict__ x,
                            const float* __restrict__ Wp,
                            const float* __restrict__ bp) {
    int n = blockIdx.x;
    int d = threadIdx.x;
    float acc = bp[d];
#pragma unroll
    for (int f = 0; f < FIN; ++f)
        acc += x[n * FIN + f] * Wp[f * DD + d];
    size_t o = (size_t)n * DD + d;
    g_h[o] = acc;
    __nv_bfloat16 hi = __float2bfloat16(acc);
    g_hh[o] = hi;
    g_hl[o] = __float2bfloat16(acc - __bfloat162float(hi));
}

// ---------------- CSR build ----------------
__global__ void hist_kernel(const int* __restrict__ ei) {
    int e = blockIdx.x * blockDim.x + threadIdx.x;
    if (e < EE) atomicAdd(&g_deg[ei[EE + e]], 1);
}

__global__ __launch_bounds__(1024) void scan_kernel() {
    __shared__ int sdeg[NN];
    __shared__ int ssum[1024];
    const int tid = threadIdx.x;
    for (int i = tid; i < NN; i += 1024) sdeg[i] = g_deg[i];
    __syncthreads();
    const int CH = (NN + 1023) / 1024;   // 10
    const int base = tid * CH;
    int sum = 0;
#pragma unroll
    for (int k = 0; k < CH; ++k) {
        int idx = base + k;
        if (idx < NN) sum += sdeg[idx];
    }
    ssum[tid] = sum;
    __syncthreads();
    for (int off = 1; off < 1024; off <<= 1) {
        int v = (tid >= off) ? ssum[tid - off] : 0;
        __syncthreads();
        ssum[tid] += v;
        __syncthreads();
    }
    int run = ssum[tid] - sum;
#pragma unroll
    for (int k = 0; k < CH; ++k) {
        int idx = base + k;
        if (idx < NN) {
            int v = sdeg[idx];
            sdeg[idx] = run;
            run += v;
        }
    }
    __syncthreads();
    for (int i = tid; i < NN; i += 1024) {
        int v = sdeg[i];
        g_rowptr[i] = v;
        g_cursor[i] = v;
    }
    if (tid == 1023) g_rowptr[NN] = ssum[1023];
}

__global__ void scatter_kernel(const int* __restrict__ ei) {
    int e = blockIdx.x * blockDim.x + threadIdx.x;
    if (e < EE) {
        int d   = ei[EE + e];
        int pos = atomicAdd(&g_cursor[d], 1);
        g_csrc[pos] = ei[e];
    }
}

// ---------------- weight transpose + hi/lo split ----------------
// g_w*[sel][j][k] = split(W[k][j])   (j = output col, k contiguous)
__global__ void conv_w_kernel(const float* __restrict__ Wlm,
                              const float* __restrict__ Wrm) {
    int j   = blockIdx.x;
    int sel = blockIdx.y;
    int k   = threadIdx.x;
    const float* W = sel ? Wrm : Wlm;
    float v = W[k * DD + j];
    __nv_bfloat16 hi = __float2bfloat16(v);
    size_t o = (size_t)sel * DD * DD + (size_t)j * DD + k;
    g_wh[o] = hi;
    g_wl[o] = __float2bfloat16(v - __bfloat162float(hi));
}

// ---------------- tensor-core GEMM: C = h @ W (split-bf16, 3 mma terms) -----
// mma.sync.aligned.m16n8k16.row.col.f32.bf16.bf16.f32 (sm_80+, ok at sm_100)
__device__ __forceinline__ void mma16816(float* c, const uint32_t* a, const uint32_t* b) {
    asm volatile(
        "mma.sync.aligned.m16n8k16.row.col.f32.bf16.bf16.f32 "
        "{%0,%1,%2,%3}, {%4,%5,%6,%7}, {%8,%9}, {%0,%1,%2,%3};"
        : "+f"(c[0]), "+f"(c[1]), "+f"(c[2]), "+f"(c[3])
        : "r"(a[0]), "r"(a[1]), "r"(a[2]), "r"(a[3]), "r"(b[0]), "r"(b[1]));
}

// Block: 128 (M) x 128 (N), 256 threads = 8 warps (4 M x 2 N), warp = 32x64.
// grid.y: bit0 = N-half (0:cols 0..127, 1:cols 128..255), bit1 = sel (xl/xr).
__global__ __launch_bounds__(256) void mma_gemm_kernel() {
    __shared__ __align__(16) __nv_bfloat16 sAh[128][16];
    __shared__ __align__(16) __nv_bfloat16 sAl[128][16];
    __shared__ __align__(16) __nv_bfloat16 sBh[128][16];
    __shared__ __align__(16) __nv_bfloat16 sBl[128][16];

    const int tid  = threadIdx.x;
    const int wid  = tid >> 5;
    const int lane = tid & 31;
    const int wm   = wid & 3;          // warp M index (0..3)
    const int wn   = wid >> 2;         // warp N index (0..1)
    const int rg   = lane >> 2;        // row in 8-group
    const int tg   = lane & 3;         // thread in group

    const int mbase   = blockIdx.x * 128;
    const int nhalf   = blockIdx.y & 1;
    const int sel     = blockIdx.y >> 1;
    const int colBase = nhalf * 128;
    float* C = sel ? g_xr : g_xl;
    const __nv_bfloat16* Wh = g_wh + (size_t)sel * DD * DD;
    const __nv_bfloat16* Wl = g_wl + (size_t)sel * DD * DD;

    // stage-load mapping: thread -> (row = tid/2, 8-bf16 half = tid&1)
    const int srow = tid >> 1;
    const int sh   = (tid & 1) * 8;
    const int grA  = mbase + srow;
    const size_t gA = (size_t)grA * DD + sh;
    const size_t gB = (size_t)(colBase + srow) * DD + sh;

    float acc[2][8][4];
#pragma unroll
    for (int mt = 0; mt < 2; ++mt)
#pragma unroll
        for (int nt = 0; nt < 8; ++nt)
#pragma unroll
            for (int q = 0; q < 4; ++q) acc[mt][nt][q] = 0.f;

    for (int kt = 0; kt < DD; kt += 16) {
        uint4 vh, vl;
        if (grA < NN) {
            vh = *(const uint4*)(g_hh + gA + kt);
            vl = *(const uint4*)(g_hl + gA + kt);
        } else {
            vh = make_uint4(0u, 0u, 0u, 0u);
            vl = vh;
        }
        *(uint4*)&sAh[srow][sh] = vh;
        *(uint4*)&sAl[srow][sh] = vl;
        *(uint4*)&sBh[srow][sh] = *(const uint4*)(Wh + gB + kt);
        *(uint4*)&sBl[srow][sh] = *(const uint4*)(Wl + gB + kt);
        __syncthreads();

        // load fragments
        uint32_t ah[2][4], al[2][4];
#pragma unroll
        for (int mt = 0; mt < 2; ++mt) {
            int r = wm * 32 + mt * 16;
            ah[mt][0] = *(const uint32_t*)&sAh[r + rg    ][tg * 2    ];
            ah[mt][1] = *(const uint32_t*)&sAh[r + rg + 8][tg * 2    ];
            ah[mt][2] = *(const uint32_t*)&sAh[r + rg    ][tg * 2 + 8];
            ah[mt][3] = *(const uint32_t*)&sAh[r + rg + 8][tg * 2 + 8];
            al[mt][0] = *(const uint32_t*)&sAl[r + rg    ][tg * 2    ];
            al[mt][1] = *(const uint32_t*)&sAl[r + rg + 8][tg * 2    ];
            al[mt][2] = *(const uint32_t*)&sAl[r + rg    ][tg * 2 + 8];
            al[mt][3] = *(const uint32_t*)&sAl[r + rg + 8][tg * 2 + 8];
        }
        uint32_t bh[8][2], bl[8][2];
#pragma unroll
        for (int nt = 0; nt < 8; ++nt) {
            int n = wn * 64 + nt * 8 + rg;
            bh[nt][0] = *(const uint32_t*)&sBh[n][tg * 2    ];
            bh[nt][1] = *(const uint32_t*)&sBh[n][tg * 2 + 8];
            bl[nt][0] = *(const uint32_t*)&sBl[n][tg * 2    ];
            bl[nt][1] = *(const uint32_t*)&sBl[n][tg * 2 + 8];
        }
#pragma unroll
        for (int mt = 0; mt < 2; ++mt)
#pragma unroll
            for (int nt = 0; nt < 8; ++nt) {
                mma16816(acc[mt][nt], ah[mt], bh[nt]);   // hi*hi
                mma16816(acc[mt][nt], ah[mt], bl[nt]);   // hi*lo
                mma16816(acc[mt][nt], al[mt], bh[nt]);   // lo*hi
            }
        __syncthreads();
    }

    // epilogue
#pragma unroll
    for (int mt = 0; mt < 2; ++mt) {
#pragma unroll
        for (int nt = 0; nt < 8; ++nt) {
            int row0 = mbase + wm * 32 + mt * 16 + rg;
            int col  = colBase + wn * 64 + nt * 8 + tg * 2;
            if (row0 < NN)
                *(float2*)&C[(size_t)row0 * DD + col] =
                    make_float2(acc[mt][nt][0], acc[mt][nt][1]);
            if (row0 + 8 < NN)
                *(float2*)&C[(size_t)(row0 + 8) * DD + col] =
                    make_float2(acc[mt][nt][2], acc[mt][nt][3]);
        }
    }
}

// ---------------- GATv2 edge softmax + aggregate (4 heads per warp) ---------
// Also refreshes the bf16 hi/lo split of g_h for the next layer's GEMM.
__global__ __launch_bounds__(256) void gat_kernel(const float* __restrict__ att_l,
                                                  const float* __restrict__ bconv_l) {
    const int w    = threadIdx.x >> 5;
    const int lane = threadIdx.x & 31;
    const int n    = blockIdx.x * 4 + (w >> 1);
    const int half = w & 1;
    const int d    = half * 128 + lane * 4;

    const int r0 = g_rowptr[n];
    const int r1 = g_rowptr[n + 1];

    const float4 xr4  = *(const float4*)&g_xr[(size_t)n * DD + d];
    const float4 att4 = *(const float4*)&att_l[d];

    float4 acc = make_float4(0.f, 0.f, 0.f, 0.f);
    float ssum = 0.f;

    for (int k = r0; k < r1; ++k) {
        int s = g_csrc[k];
        float4 xl4 = *(const float4*)&g_xl[(size_t)s * DD + d];
        float vx = xl4.x + xr4.x, vy = xl4.y + xr4.y;
        float vz = xl4.z + xr4.z, vw = xl4.w + xr4.w;
        float p = fmaxf(vx, SLOPE * vx) * att4.x
                + fmaxf(vy, SLOPE * vy) * att4.y
                + fmaxf(vz, SLOPE * vz) * att4.z
                + fmaxf(vw, SLOPE * vw) * att4.w;
        p += __shfl_xor_sync(0xffffffffu, p, 1);
        p += __shfl_xor_sync(0xffffffffu, p, 2);
        p += __shfl_xor_sync(0xffffffffu, p, 4);
        float wgt = __expf(p);
        acc.x += wgt * xl4.x; acc.y += wgt * xl4.y;
        acc.z += wgt * xl4.z; acc.w += wgt * xl4.w;
        ssum  += wgt;
    }

    const float inv = (r1 > r0) ? (1.f / ssum) : 0.f;
    const float4 bc4 = *(const float4*)&bconv_l[d];
    const size_t o = (size_t)n * DD + d;
    float4 hv = *(float4*)&g_h[o];
    hv.x += acc.x * inv + bc4.x;
    hv.y += acc.y * inv + bc4.y;
    hv.z += acc.z * inv + bc4.z;
    hv.w += acc.w * inv + bc4.w;
    *(float4*)&g_h[o] = hv;

    // bf16 hi/lo split for the next layer's tensor GEMM
    float hvv[4] = {hv.x, hv.y, hv.z, hv.w};
    __nv_bfloat16 hh[4], hl[4];
#pragma unroll
    for (int q = 0; q < 4; ++q) {
        hh[q] = __float2bfloat16(hvv[q]);
        hl[q] = __float2bfloat16(hvv[q] - __bfloat162float(hh[q]));
    }
    *(uint2*)&g_hh[o] = *(uint2*)hh;
    *(uint2*)&g_hl[o] = *(uint2*)hl;
}

// ---------------- global mean pool + counts (run-compressed atomics) --------
__global__ void pool_kernel(const int* __restrict__ batch) {
    const int d = threadIdx.x;
    const int per = (NN + gridDim.x - 1) / gridDim.x;
    int n0 = blockIdx.x * per;
    int n1 = n0 + per; if (n1 > NN) n1 = NN;
    if (n0 >= n1) return;
    int cur = batch[n0];
    float accv = 0.f;
    int   cc   = 0;
    for (int n = n0; n < n1; ++n) {
        int b = batch[n];
        if (b != cur) {
            atomicAdd(&g_pool[cur * DD + d], accv);
            if (d == 0) atomicAdd(&g_cnt[cur], (float)cc);
            accv = 0.f; cc = 0;
            cur = b;
        }
        accv += g_h[(size_t)n * DD + d];
        cc   += 1;
    }
    atomicAdd(&g_pool[cur * DD + d], accv);
    if (d == 0) atomicAdd(&g_cnt[cur], (float)cc);
}

// ---------------- prediction head ----------------
__global__ void pred_kernel(const float* __restrict__ Wpred,
                            const float* __restrict__ bpred,
                            float* __restrict__ out) {
    const int g    = threadIdx.x >> 5;
    const int lane = threadIdx.x & 31;
    float s = 0.f;
    for (int d = lane; d < DD; d += 32)
        s += g_pool[g * DD + d] * Wpred[d];
#pragma unroll
    for (int off = 16; off; off >>= 1)
        s += __shfl_xor_sync(0xffffffffu, s, off);
    if (lane == 0)
        out[g] = s / fmaxf(g_cnt[g], 1.0f) + bpred[0];
}

// ---------------- launch ----------------
extern "C" void kernel_launch(void* const* d_in, const int* in_sizes, int n_in,
                              void* d_out, int out_size) {
    const float* x     = (const float*)d_in[0];
    const int*   ei    = (const int*)  d_in[1];
    const int*   batch = (const int*)  d_in[2];
    const float* Wp    = (const float*)d_in[3];
    const float* bp    = (const float*)d_in[4];
    const float* Wl    = (const float*)d_in[5];
    const float* Wr    = (const float*)d_in[6];
    const float* att   = (const float*)d_in[7];
    const float* bconv = (const float*)d_in[8];
    const float* Wpred = (const float*)d_in[9];
    const float* bpred = (const float*)d_in[10];
    float* out = (float*)d_out;

    zero_kernel<<<64, 256>>>();
    proj_kernel<<<NN, DD>>>(x, Wp, bp);
    hist_kernel<<<(EE + 255) / 256, 256>>>(ei);
    scan_kernel<<<1, 1024>>>();
    scatter_kernel<<<(EE + 255) / 256, 256>>>(ei);

    dim3 ggrid((NN + 127) / 128, 4);   // 79 M-tiles x {nhalf, sel}
    for (int l = 0; l < LL; ++l) {
        conv_w_kernel<<<dim3(DD, 2), DD>>>(Wl + (size_t)l * DD * DD,
                                           Wr + (size_t)l * DD * DD);
        mma_gemm_kernel<<<ggrid, 256>>>();
        gat_kernel<<<NN / 4, 256>>>(att + l * HH * CC, bconv + l * DD);
    }

    pool_kernel<<<64, DD>>>(batch);
    pred_kernel<<<1, GG * 32>>>(Wpred, bpred, out);
}

// round 9
// speedup vs baseline: 1.8335x; 1.0596x over previous
#include <cuda_runtime.h>
#include <cuda_bf16.h>
#include <math.h>
#include <stdint.h>

#define NN    10000
#define EE    320000
#define FIN   7
#define DD    256
#define HH    8
#define CC    32
#define LL    2
#define GG    16
#define SLOPE 0.2f

// ---------------- scratch (static __device__, no allocation) ----------------
__device__ float g_h  [NN * DD];
__device__ float g_xl [NN * DD];
__device__ float g_xr [NN * DD];
__device__ __align__(16) __nv_bfloat16 g_hh[NN * DD];
__device__ __align__(16) __nv_bfloat16 g_hl[NN * DD];
__device__ __align__(16) __nv_bfloat16 g_wh[2 * DD * DD];   // [sel][j][k] = W[k][j]
__device__ __align__(16) __nv_bfloat16 g_wl[2 * DD * DD];
__device__ int   g_deg   [NN];
__device__ int   g_rowptr[NN + 1];
__device__ int   g_cursor[NN];
__device__ int   g_csrc  [EE];
__device__ int   g_bsum  [40];
__device__ float g_pool  [GG * DD];
__device__ float g_cnt   [GG];

// ---------------- init ----------------
__global__ void zero_kernel() {
    int i = blockIdx.x * blockDim.x + threadIdx.x;
    int stride = gridDim.x * blockDim.x;
    for (int k = i; k < NN; k += stride)      g_deg[k] = 0;
    for (int k = i; k < GG * DD; k += stride) g_pool[k] = 0.f;
    if (i < GG) g_cnt[i] = 0.f;
}

// ---------------- h = x @ Wp + bp (+ bf16 hi/lo split) ----------------
__global__ void proj_kernel(const float* __restrict__ x,
                            const float* __restrict__ Wp,
                            const float* __restrict__ bp) {
    int n = blockIdx.x;
    int d = threadIdx.x;
    float acc = bp[d];
#pragma unroll
    for (int f = 0; f < FIN; ++f)
        acc += x[n * FIN + f] * Wp[f * DD + d];
    size_t o = (size_t)n * DD + d;
    g_h[o] = acc;
    __nv_bfloat16 hi = __float2bfloat16(acc);
    g_hh[o] = hi;
    g_hl[o] = __float2bfloat16(acc - __bfloat162float(hi));
}

// ---------------- CSR build ----------------
__global__ void hist_kernel(const int* __restrict__ ei) {
    int e = blockIdx.x * blockDim.x + threadIdx.x;
    if (e < EE) atomicAdd(&g_deg[ei[EE + e]], 1);
}

// two-level scan: 40 blocks x 256 -> block-local exclusive scan + block sums
__global__ __launch_bounds__(256) void scan1_kernel() {
    __shared__ int s[256];
    const int t = threadIdx.x;
    const int i = blockIdx.x * 256 + t;
    int v = (i < NN) ? g_deg[i] : 0;
    s[t] = v;
    __syncthreads();
#pragma unroll
    for (int off = 1; off < 256; off <<= 1) {
        int u = (t >= off) ? s[t - off] : 0;
        __syncthreads();
        s[t] += u;
        __syncthreads();
    }
    if (i < NN) g_rowptr[i] = s[t] - v;      // block-local exclusive
    if (t == 255) g_bsum[blockIdx.x] = s[255];
}

__global__ __launch_bounds__(1024) void scan2_kernel() {
    __shared__ int bs[40];
    const int t = threadIdx.x;
    if (t < 40) bs[t] = g_bsum[t];
    __syncthreads();
    if (t == 0) {
        int r = 0;
#pragma unroll
        for (int j = 0; j < 40; ++j) { int v = bs[j]; bs[j] = r; r += v; }
        g_rowptr[NN] = r;
    }
    __syncthreads();
    for (int i = t; i < NN; i += 1024) {
        int v = g_rowptr[i] + bs[i >> 8];
        g_rowptr[i] = v;
        g_cursor[i] = v;
    }
}

__global__ void scatter_kernel(const int* __restrict__ ei) {
    int e = blockIdx.x * blockDim.x + threadIdx.x;
    if (e < EE) {
        int d   = ei[EE + e];
        int pos = atomicAdd(&g_cursor[d], 1);
        g_csrc[pos] = ei[e];
    }
}

// ---------------- weight transpose + hi/lo split ----------------
__global__ void conv_w_kernel(const float* __restrict__ Wlm,
                              const float* __restrict__ Wrm) {
    int j   = blockIdx.x;
    int sel = blockIdx.y;
    int k   = threadIdx.x;
    const float* W = sel ? Wrm : Wlm;
    float v = W[k * DD + j];
    __nv_bfloat16 hi = __float2bfloat16(v);
    size_t o = (size_t)sel * DD * DD + (size_t)j * DD + k;
    g_wh[o] = hi;
    g_wl[o] = __float2bfloat16(v - __bfloat162float(hi));
}

// ---------------- tensor-core GEMM: C = h @ W (split-bf16, 3 mma terms) -----
__device__ __forceinline__ void mma16816(float* c, const uint32_t* a, const uint32_t* b) {
    asm volatile(
        "mma.sync.aligned.m16n8k16.row.col.f32.bf16.bf16.f32 "
        "{%0,%1,%2,%3}, {%4,%5,%6,%7}, {%8,%9}, {%0,%1,%2,%3};"
        : "+f"(c[0]), "+f"(c[1]), "+f"(c[2]), "+f"(c[3])
        : "r"(a[0]), "r"(a[1]), "r"(a[2]), "r"(a[3]), "r"(b[0]), "r"(b[1]));
}

__global__ __launch_bounds__(256) void mma_gemm_kernel() {
    __shared__ __align__(16) __nv_bfloat16 sAh[128][16];
    __shared__ __align__(16) __nv_bfloat16 sAl[128][16];
    __shared__ __align__(16) __nv_bfloat16 sBh[128][16];
    __shared__ __align__(16) __nv_bfloat16 sBl[128][16];

    const int tid  = threadIdx.x;
    const int wid  = tid >> 5;
    const int lane = tid & 31;
    const int wm   = wid & 3;
    const int wn   = wid >> 2;
    const int rg   = lane >> 2;
    const int tg   = lane & 3;

    const int mbase   = blockIdx.x * 128;
    const int nhalf   = blockIdx.y & 1;
    const int sel     = blockIdx.y >> 1;
    const int colBase = nhalf * 128;
    float* C = sel ? g_xr : g_xl;
    const __nv_bfloat16* Wh = g_wh + (size_t)sel * DD * DD;
    const __nv_bfloat16* Wl = g_wl + (size_t)sel * DD * DD;

    const int srow = tid >> 1;
    const int sh   = (tid & 1) * 8;
    const int grA  = mbase + srow;
    const size_t gA = (size_t)grA * DD + sh;
    const size_t gB = (size_t)(colBase + srow) * DD + sh;

    float acc[2][8][4];
#pragma unroll
    for (int mt = 0; mt < 2; ++mt)
#pragma unroll
        for (int nt = 0; nt < 8; ++nt)
#pragma unroll
            for (int q = 0; q < 4; ++q) acc[mt][nt][q] = 0.f;

    for (int kt = 0; kt < DD; kt += 16) {
        uint4 vh, vl;
        if (grA < NN) {
            vh = *(const uint4*)(g_hh + gA + kt);
            vl = *(const uint4*)(g_hl + gA + kt);
        } else {
            vh = make_uint4(0u, 0u, 0u, 0u);
            vl = vh;
        }
        *(uint4*)&sAh[srow][sh] = vh;
        *(uint4*)&sAl[srow][sh] = vl;
        *(uint4*)&sBh[srow][sh] = *(const uint4*)(Wh + gB + kt);
        *(uint4*)&sBl[srow][sh] = *(const uint4*)(Wl + gB + kt);
        __syncthreads();

        uint32_t ah[2][4], al[2][4];
#pragma unroll
        for (int mt = 0; mt < 2; ++mt) {
            int r = wm * 32 + mt * 16;
            ah[mt][0] = *(const uint32_t*)&sAh[r + rg    ][tg * 2    ];
            ah[mt][1] = *(const uint32_t*)&sAh[r + rg + 8][tg * 2    ];
            ah[mt][2] = *(const uint32_t*)&sAh[r + rg    ][tg * 2 + 8];
            ah[mt][3] = *(const uint32_t*)&sAh[r + rg + 8][tg * 2 + 8];
            al[mt][0] = *(const uint32_t*)&sAl[r + rg    ][tg * 2    ];
            al[mt][1] = *(const uint32_t*)&sAl[r + rg + 8][tg * 2    ];
            al[mt][2] = *(const uint32_t*)&sAl[r + rg    ][tg * 2 + 8];
            al[mt][3] = *(const uint32_t*)&sAl[r + rg + 8][tg * 2 + 8];
        }
        uint32_t bh[8][2], bl[8][2];
#pragma unroll
        for (int nt = 0; nt < 8; ++nt) {
            int n = wn * 64 + nt * 8 + rg;
            bh[nt][0] = *(const uint32_t*)&sBh[n][tg * 2    ];
            bh[nt][1] = *(const uint32_t*)&sBh[n][tg * 2 + 8];
            bl[nt][0] = *(const uint32_t*)&sBl[n][tg * 2    ];
            bl[nt][1] = *(const uint32_t*)&sBl[n][tg * 2 + 8];
        }
#pragma unroll
        for (int mt = 0; mt < 2; ++mt)
#pragma unroll
            for (int nt = 0; nt < 8; ++nt) {
                mma16816(acc[mt][nt], ah[mt], bh[nt]);
                mma16816(acc[mt][nt], ah[mt], bl[nt]);
                mma16816(acc[mt][nt], al[mt], bh[nt]);
            }
        __syncthreads();
    }

#pragma unroll
    for (int mt = 0; mt < 2; ++mt) {
#pragma unroll
        for (int nt = 0; nt < 8; ++nt) {
            int row0 = mbase + wm * 32 + mt * 16 + rg;
            int col  = colBase + wn * 64 + nt * 8 + tg * 2;
            if (row0 < NN)
                *(float2*)&C[(size_t)row0 * DD + col] =
                    make_float2(acc[mt][nt][0], acc[mt][nt][1]);
            if (row0 + 8 < NN)
                *(float2*)&C[(size_t)(row0 + 8) * DD + col] =
                    make_float2(acc[mt][nt][2], acc[mt][nt][3]);
        }
    }
}

// ---------------- GATv2 edge softmax + aggregate (pairwise-unrolled) --------
// Warp = (node, half): 128 channels, 4 heads; lane = float4. Two edges per
// iteration -> 2 independent L2 gathers in flight before the shfl sync point.
__global__ __launch_bounds__(256) void gat_kernel(const float* __restrict__ att_l,
                                                  const float* __restrict__ bconv_l) {
    const int w    = threadIdx.x >> 5;
    const int lane = threadIdx.x & 31;
    const int n    = blockIdx.x * 4 + (w >> 1);
    const int half = w & 1;
    const int d    = half * 128 + lane * 4;

    const int r0 = g_rowptr[n];
    const int r1 = g_rowptr[n + 1];

    const float4 xr4  = *(const float4*)&g_xr[(size_t)n * DD + d];
    const float4 att4 = *(const float4*)&att_l[d];

    float4 acc = make_float4(0.f, 0.f, 0.f, 0.f);
    float ssum = 0.f;

    int k = r0;
    for (; k + 1 < r1; k += 2) {
        int s0 = g_csrc[k];
        int s1 = g_csrc[k + 1];
        float4 xa = *(const float4*)&g_xl[(size_t)s0 * DD + d];
        float4 xb = *(const float4*)&g_xl[(size_t)s1 * DD + d];

        float vax = xa.x + xr4.x, vay = xa.y + xr4.y;
        float vaz = xa.z + xr4.z, vaw = xa.w + xr4.w;
        float pa = fmaxf(vax, SLOPE * vax) * att4.x
                 + fmaxf(vay, SLOPE * vay) * att4.y
                 + fmaxf(vaz, SLOPE * vaz) * att4.z
                 + fmaxf(vaw, SLOPE * vaw) * att4.w;
        float vbx = xb.x + xr4.x, vby = xb.y + xr4.y;
        float vbz = xb.z + xr4.z, vbw = xb.w + xr4.w;
        float pb = fmaxf(vbx, SLOPE * vbx) * att4.x
                 + fmaxf(vby, SLOPE * vby) * att4.y
                 + fmaxf(vbz, SLOPE * vbz) * att4.z
                 + fmaxf(vbw, SLOPE * vbw) * att4.w;

        pa += __shfl_xor_sync(0xffffffffu, pa, 1);
        pb += __shfl_xor_sync(0xffffffffu, pb, 1);
        pa += __shfl_xor_sync(0xffffffffu, pa, 2);
        pb += __shfl_xor_sync(0xffffffffu, pb, 2);
        pa += __shfl_xor_sync(0xffffffffu, pa, 4);
        pb += __shfl_xor_sync(0xffffffffu, pb, 4);

        float wa = __expf(pa);
        float wb = __expf(pb);
        acc.x += wa * xa.x + wb * xb.x;
        acc.y += wa * xa.y + wb * xb.y;
        acc.z += wa * xa.z + wb * xb.z;
        acc.w += wa * xa.w + wb * xb.w;
        ssum  += wa + wb;
    }
    if (k < r1) {
        int s0 = g_csrc[k];
        float4 xa = *(const float4*)&g_xl[(size_t)s0 * DD + d];
        float vax = xa.x + xr4.x, vay = xa.y + xr4.y;
        float vaz = xa.z + xr4.z, vaw = xa.w + xr4.w;
        float pa = fmaxf(vax, SLOPE * vax) * att4.x
                 + fmaxf(vay, SLOPE * vay) * att4.y
                 + fmaxf(vaz, SLOPE * vaz) * att4.z
                 + fmaxf(vaw, SLOPE * vaw) * att4.w;
        pa += __shfl_xor_sync(0xffffffffu, pa, 1);
        pa += __shfl_xor_sync(0xffffffffu, pa, 2);
        pa += __shfl_xor_sync(0xffffffffu, pa, 4);
        float wa = __expf(pa);
        acc.x += wa * xa.x; acc.y += wa * xa.y;
        acc.z += wa * xa.z; acc.w += wa * xa.w;
        ssum  += wa;
    }

    const float inv = (r1 > r0) ? (1.f / ssum) : 0.f;
    const float4 bc4 = *(const float4*)&bconv_l[d];
    const size_t o = (size_t)n * DD + d;
    float4 hv = *(float4*)&g_h[o];
    hv.x += acc.x * inv + bc4.x;
    hv.y += acc.y * inv + bc4.y;
    hv.z += acc.z * inv + bc4.z;
    hv.w += acc.w * inv + bc4.w;
    *(float4*)&g_h[o] = hv;

    float hvv[4] = {hv.x, hv.y, hv.z, hv.w};
    __nv_bfloat16 hh[4], hl[4];
#pragma unroll
    for (int q = 0; q < 4; ++q) {
        hh[q] = __float2bfloat16(hvv[q]);
        hl[q] = __float2bfloat16(hvv[q] - __bfloat162float(hh[q]));
    }
    *(uint2*)&g_hh[o] = *(uint2*)hh;
    *(uint2*)&g_hl[o] = *(uint2*)hl;
}

// ---------------- global mean pool + counts (run-compressed atomics) --------
__global__ void pool_kernel(const int* __restrict__ batch) {
    const int d = threadIdx.x;
    const int per = (NN + gridDim.x - 1) / gridDim.x;
    int n0 = blockIdx.x * per;
    int n1 = n0 + per; if (n1 > NN) n1 = NN;
    if (n0 >= n1) return;
    int cur = batch[n0];
    float accv = 0.f;
    int   cc   = 0;
    for (int n = n0; n < n1; ++n) {
        int b = batch[n];
        if (b != cur) {
            atomicAdd(&g_pool[cur * DD + d], accv);
            if (d == 0) atomicAdd(&g_cnt[cur], (float)cc);
            accv = 0.f; cc = 0;
            cur = b;
        }
        accv += g_h[(size_t)n * DD + d];
        cc   += 1;
    }
    atomicAdd(&g_pool[cur * DD + d], accv);
    if (d == 0) atomicAdd(&g_cnt[cur], (float)cc);
}

// ---------------- prediction head ----------------
__global__ void pred_kernel(const float* __restrict__ Wpred,
                            const float* __restrict__ bpred,
                            float* __restrict__ out) {
    const int g    = threadIdx.x >> 5;
    const int lane = threadIdx.x & 31;
    float s = 0.f;
    for (int d = lane; d < DD; d += 32)
        s += g_pool[g * DD + d] * Wpred[d];
#pragma unroll
    for (int off = 16; off; off >>= 1)
        s += __shfl_xor_sync(0xffffffffu, s, off);
    if (lane == 0)
        out[g] = s / fmaxf(g_cnt[g], 1.0f) + bpred[0];
}

// ---------------- launch ----------------
extern "C" void kernel_launch(void* const* d_in, const int* in_sizes, int n_in,
                              void* d_out, int out_size) {
    const float* x     = (const float*)d_in[0];
    const int*   ei    = (const int*)  d_in[1];
    const int*   batch = (const int*)  d_in[2];
    const float* Wp    = (const float*)d_in[3];
    const float* bp    = (const float*)d_in[4];
    const float* Wl    = (const float*)d_in[5];
    const float* Wr    = (const float*)d_in[6];
    const float* att   = (const float*)d_in[7];
    const float* bconv = (const float*)d_in[8];
    const float* Wpred = (const float*)d_in[9];
    const float* bpred = (const float*)d_in[10];
    float* out = (float*)d_out;

    zero_kernel<<<64, 256>>>();
    proj_kernel<<<NN, DD>>>(x, Wp, bp);
    hist_kernel<<<(EE + 255) / 256, 256>>>(ei);
    scan1_kernel<<<40, 256>>>();
    scan2_kernel<<<1, 1024>>>();
    scatter_kernel<<<(EE + 255) / 256, 256>>>(ei);

    dim3 ggrid((NN + 127) / 128, 4);
    for (int l = 0; l < LL; ++l) {
        conv_w_kernel<<<dim3(DD, 2), DD>>>(Wl + (size_t)l * DD * DD,
                                           Wr + (size_t)l * DD * DD);
        mma_gemm_kernel<<<ggrid, 256>>>();
        gat_kernel<<<NN / 4, 256>>>(att + l * HH * CC, bconv + l * DD);
    }

    pool_kernel<<<64, DD>>>(batch);
    pred_kernel<<<1, GG * 32>>>(Wpred, bpred, out);
}